// round 1
// baseline (speedup 1.0000x reference)
#include <cuda_runtime.h>
#include <math.h>

// Problem constants
#define Bq 8
#define Nn 768
#define Tt 769
#define Dd 256
#define Hh 8
#define DKk 32
#define Ll 6
#define Ff 128
#define Mrows (Bq*Tt)   // 6152

// ---- scratch (device globals; no allocation allowed) ----
__device__ float g_bias[Bq*Tt*Tt];     // (B,T,T) attention bias  ~18.9MB
__device__ float g_x  [Mrows*Dd];      // residual stream
__device__ float g_xn [Mrows*Dd];      // layernorm output
__device__ float g_q  [Mrows*Dd];
__device__ float g_k  [Mrows*Dd];
__device__ float g_v  [Mrows*Dd];
__device__ float g_att[Mrows*Dd];      // attention output (pre O-proj)
__device__ float g_m1 [Mrows*Dd];      // MLP hidden (Dm == D)
__device__ float g_deg[Bq*Nn];
__device__ float g_degmax[Bq];

// ---------------------------------------------------------------------------
// degree: one warp per (b,i) row of adj
__global__ void deg_kernel(const int* __restrict__ adj) {
    int row  = blockIdx.x * 8 + (threadIdx.x >> 5);   // 0..B*N-1
    int lane = threadIdx.x & 31;
    const int* a = adj + (size_t)row * Nn;
    float s = 0.f;
    #pragma unroll
    for (int k2 = 0; k2 < Nn / 32; k2++) s += (float)a[lane + 32 * k2];
    #pragma unroll
    for (int o = 16; o; o >>= 1) s += __shfl_xor_sync(0xffffffffu, s, o);
    if (lane == 0) g_deg[row] = s;
}

__global__ void degmax_kernel() {
    int b = blockIdx.x, tid = threadIdx.x;
    float m = 0.f;
    for (int i = tid; i < Nn; i += 256) m = fmaxf(m, g_deg[b * Nn + i]);
    __shared__ float sm[256];
    sm[tid] = m; __syncthreads();
    for (int s = 128; s; s >>= 1) {
        if (tid < s) sm[tid] = fmaxf(sm[tid], sm[tid + s]);
        __syncthreads();
    }
    if (tid == 0) g_degmax[b] = sm[0];
}

// bias inner block: e = oh.etw - gamma*dist (+noedge if adj==0) + deg_scale*degnorm
__global__ void bias_edge_kernel(const int* __restrict__ adj,
                                 const float* __restrict__ dist,
                                 const float* __restrict__ eoh,
                                 const float* __restrict__ etw,
                                 const float* __restrict__ noedge,
                                 const float* __restrict__ degscale,
                                 const float* __restrict__ gamma) {
    int i = blockIdx.x, b = blockIdx.y;
    float e0 = etw[0], e1 = etw[1], e2 = etw[2], e3 = etw[3];
    float ne = noedge[0], ds = degscale[0], ga = gamma[0];
    float di = g_deg[b * Nn + i];
    float inv_dmx = 1.f / (g_degmax[b] + 1e-6f);
    size_t base = ((size_t)b * Nn + i) * Nn;
    for (int j = threadIdx.x; j < Nn; j += 256) {
        const float* eo = eoh + (base + j) * 4;
        float e = eo[0] * e0 + eo[1] * e1 + eo[2] * e2 + eo[3] * e3 - ga * dist[base + j];
        if (adj[base + j] == 0) e += ne;
        e += ds * (di + g_deg[b * Nn + j]) * inv_dmx;
        g_bias[(size_t)b * Tt * Tt + (size_t)(i + 1) * Tt + (j + 1)] = e;
    }
}

__global__ void bias_fill_kernel(const float* v2n, const float* n2v, const float* vself) {
    int b = blockIdx.x;
    float a = v2n[0], c = n2v[0];
    size_t base = (size_t)b * Tt * Tt;
    for (int t = threadIdx.x + 1; t < Tt; t += 256) {
        g_bias[base + t]             = a;   // [0][t]
        g_bias[base + (size_t)t * Tt] = c;  // [t][0]
    }
    if (threadIdx.x == 0) g_bias[base] = vself[0];
}

// ---------------------------------------------------------------------------
// x init: row 0 = cls, rows 1.. = node_feats @ W(128x256) + b
__global__ void proj_kernel(const float* __restrict__ nf, const float* __restrict__ W,
                            const float* __restrict__ bb, const float* __restrict__ cls) {
    int t = blockIdx.x, b = blockIdx.y, tid = threadIdx.x;
    if (t == 0) { g_x[((size_t)b * Tt) * Dd + tid] = cls[tid]; return; }
    __shared__ float sm[Ff];
    if (tid < Ff) sm[tid] = nf[((size_t)b * Nn + (t - 1)) * Ff + tid];
    __syncthreads();
    float a = bb[tid];
    #pragma unroll 8
    for (int k2 = 0; k2 < Ff; k2++) a = fmaf(sm[k2], W[k2 * Dd + tid], a);
    g_x[((size_t)b * Tt + t) * Dd + tid] = a;
}

// ---------------------------------------------------------------------------
// LayerNorm: one warp per row (D=256 -> 8 elems/lane)
__global__ void ln_kernel(const float* __restrict__ x, const float* __restrict__ g,
                          const float* __restrict__ bb, float* __restrict__ xn) {
    int row  = blockIdx.x * 8 + (threadIdx.x >> 5);
    int lane = threadIdx.x & 31;
    const float* xr = x + (size_t)row * Dd;
    float v[8], s = 0.f, s2 = 0.f;
    #pragma unroll
    for (int k2 = 0; k2 < 8; k2++) {
        v[k2] = xr[lane + 32 * k2];
        s += v[k2]; s2 += v[k2] * v[k2];
    }
    #pragma unroll
    for (int o = 16; o; o >>= 1) {
        s  += __shfl_xor_sync(0xffffffffu, s, o);
        s2 += __shfl_xor_sync(0xffffffffu, s2, o);
    }
    float mean = s * (1.f / Dd);
    float var  = s2 * (1.f / Dd) - mean * mean;
    float rs = rsqrtf(var + 1e-5f);
    float* orow = xn + (size_t)row * Dd;
    #pragma unroll
    for (int k2 = 0; k2 < 8; k2++) {
        int d = lane + 32 * k2;
        orow[d] = (v[k2] - mean) * rs * g[d] + bb[d];
    }
}

// ---------------------------------------------------------------------------
// GEMM: C(M x 256) = A(M x 256) @ W(256 x 256) + bias ; epilogue:
//   EPI=0: store   EPI=1: GELU(exact) store   EPI=2: residual add (C += ...)
template<int EPI>
__global__ void gemm256_kernel(const float* __restrict__ A, const float* __restrict__ W,
                               const float* __restrict__ bias, float* __restrict__ C) {
    const int M = Mrows;
    int n0 = blockIdx.x * 64, m0 = blockIdx.y * 64;
    int tid = threadIdx.x;
    int tx = tid & 15, ty = tid >> 4;
    __shared__ float As[16][65];
    __shared__ float Ws[16][65];
    float acc[4][4] = {};
    int arow = tid >> 2, aquad = tid & 3;
    int wk = tid >> 4, wn = (tid & 15) * 4;
    for (int k0 = 0; k0 < 256; k0 += 16) {
        float4 av = make_float4(0.f, 0.f, 0.f, 0.f);
        if (m0 + arow < M)
            av = *(const float4*)(A + (size_t)(m0 + arow) * 256 + k0 + aquad * 4);
        As[aquad * 4 + 0][arow] = av.x;
        As[aquad * 4 + 1][arow] = av.y;
        As[aquad * 4 + 2][arow] = av.z;
        As[aquad * 4 + 3][arow] = av.w;
        float4 wv = *(const float4*)(W + (size_t)(k0 + wk) * 256 + n0 + wn);
        Ws[wk][wn + 0] = wv.x; Ws[wk][wn + 1] = wv.y;
        Ws[wk][wn + 2] = wv.z; Ws[wk][wn + 3] = wv.w;
        __syncthreads();
        #pragma unroll
        for (int k2 = 0; k2 < 16; k2++) {
            float a_[4], b_[4];
            #pragma unroll
            for (int i = 0; i < 4; i++) a_[i] = As[k2][ty * 4 + i];
            #pragma unroll
            for (int j = 0; j < 4; j++) b_[j] = Ws[k2][tx * 4 + j];
            #pragma unroll
            for (int i = 0; i < 4; i++)
                #pragma unroll
                for (int j = 0; j < 4; j++)
                    acc[i][j] = fmaf(a_[i], b_[j], acc[i][j]);
        }
        __syncthreads();
    }
    #pragma unroll
    for (int i = 0; i < 4; i++) {
        int m = m0 + ty * 4 + i;
        if (m >= M) break;
        float* crow = C + (size_t)m * 256 + n0;
        #pragma unroll
        for (int j = 0; j < 4; j++) {
            float val = acc[i][j] + bias[n0 + tx * 4 + j];
            if (EPI == 1) val = 0.5f * val * (1.f + erff(val * 0.70710678118654752f));
            if (EPI == 2) val += crow[tx * 4 + j];
            crow[tx * 4 + j] = val;
        }
    }
}

// ---------------------------------------------------------------------------
// Flash attention: DK=32 -> lane d holds q[d]/acc[d]; warp owns 8 query rows.
// Block = 8 warps = 64 query rows of one (b,h). K/V staged in smem 32-key tiles.
__global__ void attn_kernel(const float* __restrict__ q, const float* __restrict__ k,
                            const float* __restrict__ v, const float* __restrict__ bias,
                            float* __restrict__ out) {
    int bh = blockIdx.x; int b = bh >> 3; int h = bh & 7;
    int warp = threadIdx.x >> 5, lane = threadIdx.x & 31;
    int q0 = blockIdx.y * 64 + warp * 8;
    const float scale = 0.17677669529663687f;  // 1/sqrt(32)
    float qreg[8], m[8], l[8], acc[8];
    #pragma unroll
    for (int r = 0; r < 8; r++) {
        int qr = q0 + r;
        qreg[r] = (qr < Tt) ? q[((size_t)(b * Tt + qr)) * Dd + h * 32 + lane] * scale : 0.f;
        m[r] = -1e30f; l[r] = 0.f; acc[r] = 0.f;
    }
    __shared__ float Ksm[32][33], Vsm[32][33];
    const float* kb = k + (size_t)b * Tt * Dd + h * 32;
    const float* vb = v + (size_t)b * Tt * Dd + h * 32;
    const float* biasb = bias + (size_t)b * Tt * Tt;

    for (int j0 = 0; j0 < Tt; j0 += 32) {
        __syncthreads();
        #pragma unroll
        for (int t2 = 0; t2 < 4; t2++) {
            int j = warp + t2 * 8;
            int gj = j0 + j;
            float kv = 0.f, vv = 0.f;
            if (gj < Tt) { kv = kb[(size_t)gj * Dd + lane]; vv = vb[(size_t)gj * Dd + lane]; }
            Ksm[j][lane] = kv; Vsm[j][lane] = vv;
        }
        __syncthreads();

        int gjl = j0 + lane;
        float s[8];
        #pragma unroll
        for (int r = 0; r < 8; r++) {
            int qr = q0 + r;
            s[r] = (qr < Tt && gjl < Tt) ? biasb[(size_t)qr * Tt + gjl] : -1e30f;
        }
        #pragma unroll
        for (int d = 0; d < 32; d++) {
            float kd = Ksm[lane][d];
            #pragma unroll
            for (int r = 0; r < 8; r++)
                s[r] = fmaf(__shfl_sync(0xffffffffu, qreg[r], d), kd, s[r]);
        }
        float p[8];
        #pragma unroll
        for (int r = 0; r < 8; r++) {
            float smx = s[r];
            #pragma unroll
            for (int o = 16; o; o >>= 1) smx = fmaxf(smx, __shfl_xor_sync(0xffffffffu, smx, o));
            float mn = fmaxf(m[r], smx);
            p[r] = __expf(s[r] - mn);
            float corr = __expf(m[r] - mn);
            float ps = p[r];
            #pragma unroll
            for (int o = 16; o; o >>= 1) ps += __shfl_xor_sync(0xffffffffu, ps, o);
            l[r] = l[r] * corr + ps;
            acc[r] *= corr;
            m[r] = mn;
        }
        #pragma unroll
        for (int j = 0; j < 32; j++) {
            float vv = Vsm[j][lane];
            #pragma unroll
            for (int r = 0; r < 8; r++)
                acc[r] = fmaf(__shfl_sync(0xffffffffu, p[r], j), vv, acc[r]);
        }
    }
    #pragma unroll
    for (int r = 0; r < 8; r++) {
        int qr = q0 + r;
        if (qr < Tt)
            out[((size_t)(b * Tt + qr)) * Dd + h * 32 + lane] = acc[r] / l[r];
    }
}

__global__ void copy_kernel(float* __restrict__ out) {
    int i = blockIdx.x * 256 + threadIdx.x;
    if (i < Mrows * Dd) out[i] = g_x[i];
}

// ---------------------------------------------------------------------------
extern "C" void kernel_launch(void* const* d_in, const int* in_sizes, int n_in,
                              void* d_out, int out_size) {
    const float* nf       = (const float*)d_in[0];
    const int*   adj      = (const int*)  d_in[1];
    const float* dist     = (const float*)d_in[2];
    const float* eoh      = (const float*)d_in[3];
    const float* npw      = (const float*)d_in[4];
    const float* npb      = (const float*)d_in[5];
    const float* cls      = (const float*)d_in[6];
    const float* etw      = (const float*)d_in[7];
    const float* noedge   = (const float*)d_in[8];
    const float* degscale = (const float*)d_in[9];
    const float* gamma    = (const float*)d_in[10];
    const float* v2n      = (const float*)d_in[11];
    const float* n2v      = (const float*)d_in[12];
    const float* vself    = (const float*)d_in[13];
    const float* ln1g = (const float*)d_in[14]; const float* ln1b = (const float*)d_in[15];
    const float* qw   = (const float*)d_in[16]; const float* qb   = (const float*)d_in[17];
    const float* kw   = (const float*)d_in[18]; const float* kb   = (const float*)d_in[19];
    const float* vw   = (const float*)d_in[20]; const float* vb   = (const float*)d_in[21];
    const float* ow   = (const float*)d_in[22]; const float* ob   = (const float*)d_in[23];
    const float* ln2g = (const float*)d_in[24]; const float* ln2b = (const float*)d_in[25];
    const float* fc1w = (const float*)d_in[26]; const float* fc1b = (const float*)d_in[27];
    const float* fc2w = (const float*)d_in[28]; const float* fc2b = (const float*)d_in[29];

    float *p_x, *p_xn, *p_q, *p_k, *p_v, *p_att, *p_m1, *p_bias;
    cudaGetSymbolAddress((void**)&p_x,   g_x);
    cudaGetSymbolAddress((void**)&p_xn,  g_xn);
    cudaGetSymbolAddress((void**)&p_q,   g_q);
    cudaGetSymbolAddress((void**)&p_k,   g_k);
    cudaGetSymbolAddress((void**)&p_v,   g_v);
    cudaGetSymbolAddress((void**)&p_att, g_att);
    cudaGetSymbolAddress((void**)&p_m1,  g_m1);
    cudaGetSymbolAddress((void**)&p_bias, g_bias);

    // bias construction
    deg_kernel<<<(Bq * Nn) / 8, 256>>>(adj);
    degmax_kernel<<<Bq, 256>>>();
    bias_edge_kernel<<<dim3(Nn, Bq), 256>>>(adj, dist, eoh, etw, noedge, degscale, gamma);
    bias_fill_kernel<<<Bq, 256>>>(v2n, n2v, vself);

    // input projection + cls prepend
    proj_kernel<<<dim3(Tt, Bq), 256>>>(nf, npw, npb, cls);

    dim3 ggrid(4, (Mrows + 63) / 64);  // (4, 97)
    for (int l = 0; l < Ll; l++) {
        size_t wo = (size_t)l * Dd * Dd;
        size_t bo = (size_t)l * Dd;
        ln_kernel<<<Mrows / 8, 256>>>(p_x, ln1g + bo, ln1b + bo, p_xn);
        gemm256_kernel<0><<<ggrid, 256>>>(p_xn, qw + wo, qb + bo, p_q);
        gemm256_kernel<0><<<ggrid, 256>>>(p_xn, kw + wo, kb + bo, p_k);
        gemm256_kernel<0><<<ggrid, 256>>>(p_xn, vw + wo, vb + bo, p_v);
        attn_kernel<<<dim3(Bq * Hh, (Tt + 63) / 64), 256>>>(p_q, p_k, p_v, p_bias, p_att);
        gemm256_kernel<2><<<ggrid, 256>>>(p_att, ow + wo, ob + bo, p_x);
        ln_kernel<<<Mrows / 8, 256>>>(p_x, ln2g + bo, ln2b + bo, p_xn);
        gemm256_kernel<1><<<ggrid, 256>>>(p_xn, fc1w + wo, fc1b + bo, p_m1);
        gemm256_kernel<2><<<ggrid, 256>>>(p_m1, fc2w + wo, fc2b + bo, p_x);
    }
    copy_kernel<<<(Mrows * Dd + 255) / 256, 256>>>((float*)d_out);
}

// round 2
// speedup vs baseline: 2.7011x; 2.7011x over previous
#include <cuda_runtime.h>
#include <math.h>

// Problem constants
#define Bq 8
#define Nn 768
#define Tt 769
#define Dd 256
#define Hh 8
#define Ll 6
#define Ff 128
#define Mrows (Bq*Tt)   // 6152

// ---- scratch (device globals; no allocation allowed) ----
__device__ float g_bias[Bq*Tt*Tt];
__device__ float g_x  [Mrows*Dd];
__device__ float g_xn [Mrows*Dd];
__device__ float g_q  [Mrows*Dd];
__device__ float g_k  [Mrows*Dd];
__device__ float g_v  [Mrows*Dd];
__device__ float g_att[Mrows*Dd];
__device__ float g_m1 [Mrows*Dd];
__device__ float g_deg[Bq*Nn];
__device__ float g_degmax[Bq];

// ---------------------------------------------------------------------------
__device__ __forceinline__ unsigned f2tf(float x) {
    unsigned u; asm("cvt.rna.tf32.f32 %0, %1;" : "=r"(u) : "f"(x)); return u;
}
__device__ __forceinline__ void mma_tf32(float* d,
                                         unsigned a0, unsigned a1, unsigned a2, unsigned a3,
                                         unsigned b0, unsigned b1) {
    asm volatile("mma.sync.aligned.m16n8k8.row.col.f32.tf32.tf32.f32 "
                 "{%0,%1,%2,%3}, {%4,%5,%6,%7}, {%8,%9}, {%0,%1,%2,%3};\n"
                 : "+f"(d[0]), "+f"(d[1]), "+f"(d[2]), "+f"(d[3])
                 : "r"(a0), "r"(a1), "r"(a2), "r"(a3), "r"(b0), "r"(b1));
}

// ---------------------------------------------------------------------------
// degree: one warp per (b,i) row of adj
__global__ void deg_kernel(const int* __restrict__ adj) {
    int row  = blockIdx.x * 8 + (threadIdx.x >> 5);
    int lane = threadIdx.x & 31;
    const int* a = adj + (size_t)row * Nn;
    float s = 0.f;
    #pragma unroll
    for (int k2 = 0; k2 < Nn / 32; k2++) s += (float)a[lane + 32 * k2];
    #pragma unroll
    for (int o = 16; o; o >>= 1) s += __shfl_xor_sync(0xffffffffu, s, o);
    if (lane == 0) g_deg[row] = s;
}

__global__ void degmax_kernel() {
    int b = blockIdx.x, tid = threadIdx.x;
    float m = 0.f;
    for (int i = tid; i < Nn; i += 256) m = fmaxf(m, g_deg[b * Nn + i]);
    __shared__ float sm[256];
    sm[tid] = m; __syncthreads();
    for (int s = 128; s; s >>= 1) {
        if (tid < s) sm[tid] = fmaxf(sm[tid], sm[tid + s]);
        __syncthreads();
    }
    if (tid == 0) g_degmax[b] = sm[0];
}

__global__ void bias_edge_kernel(const int* __restrict__ adj,
                                 const float* __restrict__ dist,
                                 const float* __restrict__ eoh,
                                 const float* __restrict__ etw,
                                 const float* __restrict__ noedge,
                                 const float* __restrict__ degscale,
                                 const float* __restrict__ gamma) {
    int i = blockIdx.x, b = blockIdx.y;
    float e0 = etw[0], e1 = etw[1], e2 = etw[2], e3 = etw[3];
    float ne = noedge[0], ds = degscale[0], ga = gamma[0];
    float di = g_deg[b * Nn + i];
    float inv_dmx = 1.f / (g_degmax[b] + 1e-6f);
    size_t base = ((size_t)b * Nn + i) * Nn;
    for (int j = threadIdx.x; j < Nn; j += 256) {
        const float* eo = eoh + (base + j) * 4;
        float e = eo[0] * e0 + eo[1] * e1 + eo[2] * e2 + eo[3] * e3 - ga * dist[base + j];
        if (adj[base + j] == 0) e += ne;
        e += ds * (di + g_deg[b * Nn + j]) * inv_dmx;
        g_bias[(size_t)b * Tt * Tt + (size_t)(i + 1) * Tt + (j + 1)] = e;
    }
}

__global__ void bias_fill_kernel(const float* v2n, const float* n2v, const float* vself) {
    int b = blockIdx.x;
    float a = v2n[0], c = n2v[0];
    size_t base = (size_t)b * Tt * Tt;
    for (int t = threadIdx.x + 1; t < Tt; t += 256) {
        g_bias[base + t]              = a;
        g_bias[base + (size_t)t * Tt] = c;
    }
    if (threadIdx.x == 0) g_bias[base] = vself[0];
}

// ---------------------------------------------------------------------------
__global__ void proj_kernel(const float* __restrict__ nf, const float* __restrict__ W,
                            const float* __restrict__ bb, const float* __restrict__ cls) {
    int t = blockIdx.x, b = blockIdx.y, tid = threadIdx.x;
    if (t == 0) { g_x[((size_t)b * Tt) * Dd + tid] = cls[tid]; return; }
    __shared__ float sm[Ff];
    if (tid < Ff) sm[tid] = nf[((size_t)b * Nn + (t - 1)) * Ff + tid];
    __syncthreads();
    float a = bb[tid];
    #pragma unroll 8
    for (int k2 = 0; k2 < Ff; k2++) a = fmaf(sm[k2], W[k2 * Dd + tid], a);
    g_x[((size_t)b * Tt + t) * Dd + tid] = a;
}

// ---------------------------------------------------------------------------
__global__ void ln_kernel(const float* __restrict__ x, const float* __restrict__ g,
                          const float* __restrict__ bb, float* __restrict__ xn) {
    int row  = blockIdx.x * 8 + (threadIdx.x >> 5);
    int lane = threadIdx.x & 31;
    const float* xr = x + (size_t)row * Dd;
    float v[8], s = 0.f, s2 = 0.f;
    #pragma unroll
    for (int k2 = 0; k2 < 8; k2++) {
        v[k2] = xr[lane + 32 * k2];
        s += v[k2]; s2 += v[k2] * v[k2];
    }
    #pragma unroll
    for (int o = 16; o; o >>= 1) {
        s  += __shfl_xor_sync(0xffffffffu, s, o);
        s2 += __shfl_xor_sync(0xffffffffu, s2, o);
    }
    float mean = s * (1.f / Dd);
    float var  = s2 * (1.f / Dd) - mean * mean;
    float rs = rsqrtf(var + 1e-5f);
    float* orow = xn + (size_t)row * Dd;
    #pragma unroll
    for (int k2 = 0; k2 < 8; k2++) {
        int d = lane + 32 * k2;
        orow[d] = (v[k2] - mean) * rs * g[d] + bb[d];
    }
}

// ---------------------------------------------------------------------------
// Tensor-core GEMM (tf32): C(M x 256) = A(M x 256) @ W(256x256) + bias
// BM=64, BN=64, BK=32; 4 warps, each 32x32 (2 mfrags x 4 nfrags of m16n8k8)
// EPI: 0=store  1=GELU  2=residual add
template<int EPI>
__global__ void gemm_tc(const float* __restrict__ A, const float* __restrict__ W,
                        const float* __restrict__ bias, float* __restrict__ C) {
    const int M = Mrows;
    int n0 = blockIdx.x * 64, m0 = blockIdx.y * 64;
    int tid = threadIdx.x, w = tid >> 5, lane = tid & 31;
    int g = lane >> 2, t = lane & 3;
    int wm = (w >> 1) * 32, wn = (w & 1) * 32;
    // bank-conflict-free fragment layouts:
    //   As stride 36 (=4 mod 32): bank(a0) = 4*g + t = lane
    //   Ws stride 72 (=8 mod 32): bank(b0) = 8*t + g
    __shared__ unsigned As[64][36];
    __shared__ unsigned Ws[32][72];
    float acc[2][4][4];
    #pragma unroll
    for (int i = 0; i < 2; i++)
        #pragma unroll
        for (int j = 0; j < 4; j++)
            #pragma unroll
            for (int c = 0; c < 4; c++) acc[i][j][c] = 0.f;

    for (int k0 = 0; k0 < 256; k0 += 32) {
        #pragma unroll
        for (int r = 0; r < 4; r++) {
            int idx = tid + 128 * r;
            // A tile 64x32
            int m = idx >> 3, k4 = (idx & 7) << 2;
            float4 av = make_float4(0.f, 0.f, 0.f, 0.f);
            if (m0 + m < M) av = *(const float4*)(A + (size_t)(m0 + m) * 256 + k0 + k4);
            uint4 at = make_uint4(f2tf(av.x), f2tf(av.y), f2tf(av.z), f2tf(av.w));
            *(uint4*)&As[m][k4] = at;
            // W tile 32x64
            int kk = idx >> 4, n4 = (idx & 15) << 2;
            float4 wv = *(const float4*)(W + (size_t)(k0 + kk) * 256 + n0 + n4);
            uint4 wt = make_uint4(f2tf(wv.x), f2tf(wv.y), f2tf(wv.z), f2tf(wv.w));
            *(uint4*)&Ws[kk][n4] = wt;
        }
        __syncthreads();
        #pragma unroll
        for (int ks = 0; ks < 4; ks++) {
            int kb = ks * 8;
            unsigned a[2][4];
            #pragma unroll
            for (int mf = 0; mf < 2; mf++) {
                int mb = wm + mf * 16;
                a[mf][0] = As[mb + g][kb + t];
                a[mf][1] = As[mb + g + 8][kb + t];
                a[mf][2] = As[mb + g][kb + t + 4];
                a[mf][3] = As[mb + g + 8][kb + t + 4];
            }
            #pragma unroll
            for (int nf = 0; nf < 4; nf++) {
                unsigned b0 = Ws[kb + t][wn + nf * 8 + g];
                unsigned b1 = Ws[kb + t + 4][wn + nf * 8 + g];
                #pragma unroll
                for (int mf = 0; mf < 2; mf++)
                    mma_tf32(acc[mf][nf], a[mf][0], a[mf][1], a[mf][2], a[mf][3], b0, b1);
            }
        }
        __syncthreads();
    }
    // epilogue
    #pragma unroll
    for (int mf = 0; mf < 2; mf++) {
        int row0 = m0 + wm + mf * 16 + g;
        #pragma unroll
        for (int nf = 0; nf < 4; nf++) {
            int col = n0 + wn + nf * 8 + 2 * t;
            float bv0 = bias[col], bv1 = bias[col + 1];
            #pragma unroll
            for (int half = 0; half < 2; half++) {
                int row = row0 + half * 8;
                if (row >= M) continue;
                float v0 = acc[mf][nf][half * 2 + 0] + bv0;
                float v1 = acc[mf][nf][half * 2 + 1] + bv1;
                float* cp = C + (size_t)row * 256 + col;
                if (EPI == 1) {
                    v0 = 0.5f * v0 * (1.f + erff(v0 * 0.70710678118654752f));
                    v1 = 0.5f * v1 * (1.f + erff(v1 * 0.70710678118654752f));
                }
                if (EPI == 2) { v0 += cp[0]; v1 += cp[1]; }
                *(float2*)cp = make_float2(v0, v1);
            }
        }
    }
}

// ---------------------------------------------------------------------------
// Tensor-core flash attention (tf32). Block = (b,h) x 64-q-row tile, 4 warps.
// Each warp owns 16 q rows. S = Q K^T + bias via mma; online softmax on C
// fragments; P staged to per-warp smem; O += P V via mma.
__global__ void attn_tc(const float* __restrict__ q, const float* __restrict__ k,
                        const float* __restrict__ v, const float* __restrict__ bias,
                        float* __restrict__ out) {
    int b = blockIdx.x >> 3, h = blockIdx.x & 7;
    int q0 = blockIdx.y * 64;
    int tid = threadIdx.x, w = tid >> 5, lane = tid & 31;
    int g = lane >> 2, t = lane & 3;

    __shared__ unsigned Qs[64][36];      // [row][feat]   bank 4m+k
    __shared__ unsigned Ks[32][72];      // [feat][key]   bank 8k+n
    __shared__ unsigned Vs[64][40];      // [key][feat]   bank 8k+n
    __shared__ unsigned Ps[4][16][68];   // per-warp P    bank 4m+k

    const float scale = 0.17677669529663687f;  // 1/sqrt(32)
    const float* kb_ = k + (size_t)b * Tt * Dd + h * 32;
    const float* vb_ = v + (size_t)b * Tt * Dd + h * 32;
    const float* biasb = bias + (size_t)b * Tt * Tt;

    // stage Q (scaled, tf32)
    #pragma unroll
    for (int r = 0; r < 4; r++) {
        int idx = tid + 128 * r;
        int m = idx >> 3, k4 = (idx & 7) << 2;
        float4 qv = make_float4(0.f, 0.f, 0.f, 0.f);
        int qr = q0 + m;
        if (qr < Tt) qv = *(const float4*)(q + ((size_t)(b * Tt + qr)) * 256 + h * 32 + k4);
        uint4 qt = make_uint4(f2tf(qv.x * scale), f2tf(qv.y * scale),
                              f2tf(qv.z * scale), f2tf(qv.w * scale));
        *(uint4*)&Qs[m][k4] = qt;
    }
    __syncthreads();
    int mb = w * 16;
    unsigned qa[4][4];
    #pragma unroll
    for (int ks = 0; ks < 4; ks++) {
        int kb2 = ks * 8;
        qa[ks][0] = Qs[mb + g][kb2 + t];
        qa[ks][1] = Qs[mb + g + 8][kb2 + t];
        qa[ks][2] = Qs[mb + g][kb2 + t + 4];
        qa[ks][3] = Qs[mb + g + 8][kb2 + t + 4];
    }

    float mrow[2] = {-1e30f, -1e30f}, lrow[2] = {0.f, 0.f};
    float oacc[4][4];
    #pragma unroll
    for (int i = 0; i < 4; i++)
        #pragma unroll
        for (int c = 0; c < 4; c++) oacc[i][c] = 0.f;

    int r0g = q0 + mb + g, r1g = r0g + 8;

    for (int j0 = 0; j0 < Tt; j0 += 64) {
        __syncthreads();
        // load K (transposed) and V tiles
        #pragma unroll
        for (int r = 0; r < 4; r++) {
            int idx = tid + 128 * r;
            int key = idx >> 3, f4 = (idx & 7) << 2;
            int gj = j0 + key;
            float4 kv = make_float4(0.f, 0.f, 0.f, 0.f);
            float4 vv = make_float4(0.f, 0.f, 0.f, 0.f);
            if (gj < Tt) {
                kv = *(const float4*)(kb_ + (size_t)gj * 256 + f4);
                vv = *(const float4*)(vb_ + (size_t)gj * 256 + f4);
            }
            Ks[f4 + 0][key] = f2tf(kv.x);
            Ks[f4 + 1][key] = f2tf(kv.y);
            Ks[f4 + 2][key] = f2tf(kv.z);
            Ks[f4 + 3][key] = f2tf(kv.w);
            uint4 vt = make_uint4(f2tf(vv.x), f2tf(vv.y), f2tf(vv.z), f2tf(vv.w));
            *(uint4*)&Vs[key][f4] = vt;
        }
        __syncthreads();

        // S init = bias (OOB -> -1e30)
        float s[8][4];
        #pragma unroll
        for (int nf = 0; nf < 8; nf++) {
            int col0 = j0 + nf * 8 + 2 * t;
            #pragma unroll
            for (int c = 0; c < 2; c++) {
                int col = col0 + c;
                s[nf][c]     = (r0g < Tt && col < Tt) ? biasb[(size_t)r0g * Tt + col] : -1e30f;
                s[nf][2 + c] = (r1g < Tt && col < Tt) ? biasb[(size_t)r1g * Tt + col] : -1e30f;
            }
        }
        // S += Q K^T
        #pragma unroll
        for (int ks = 0; ks < 4; ks++) {
            int kb2 = ks * 8;
            #pragma unroll
            for (int nf = 0; nf < 8; nf++) {
                unsigned b0 = Ks[kb2 + t][nf * 8 + g];
                unsigned b1 = Ks[kb2 + t + 4][nf * 8 + g];
                mma_tf32(s[nf], qa[ks][0], qa[ks][1], qa[ks][2], qa[ks][3], b0, b1);
            }
        }
        // online softmax (rows g, g+8)
        float tmax[2] = {-1e30f, -1e30f};
        #pragma unroll
        for (int nf = 0; nf < 8; nf++) {
            tmax[0] = fmaxf(tmax[0], fmaxf(s[nf][0], s[nf][1]));
            tmax[1] = fmaxf(tmax[1], fmaxf(s[nf][2], s[nf][3]));
        }
        #pragma unroll
        for (int o = 1; o <= 2; o <<= 1) {
            tmax[0] = fmaxf(tmax[0], __shfl_xor_sync(0xffffffffu, tmax[0], o));
            tmax[1] = fmaxf(tmax[1], __shfl_xor_sync(0xffffffffu, tmax[1], o));
        }
        float mn0 = fmaxf(mrow[0], tmax[0]), mn1 = fmaxf(mrow[1], tmax[1]);
        float corr0 = __expf(mrow[0] - mn0), corr1 = __expf(mrow[1] - mn1);
        mrow[0] = mn0; mrow[1] = mn1;
        float sum0 = 0.f, sum1 = 0.f;
        #pragma unroll
        for (int nf = 0; nf < 8; nf++) {
            s[nf][0] = __expf(s[nf][0] - mn0); sum0 += s[nf][0];
            s[nf][1] = __expf(s[nf][1] - mn0); sum0 += s[nf][1];
            s[nf][2] = __expf(s[nf][2] - mn1); sum1 += s[nf][2];
            s[nf][3] = __expf(s[nf][3] - mn1); sum1 += s[nf][3];
        }
        #pragma unroll
        for (int o = 1; o <= 2; o <<= 1) {
            sum0 += __shfl_xor_sync(0xffffffffu, sum0, o);
            sum1 += __shfl_xor_sync(0xffffffffu, sum1, o);
        }
        lrow[0] = lrow[0] * corr0 + sum0;
        lrow[1] = lrow[1] * corr1 + sum1;
        #pragma unroll
        for (int i = 0; i < 4; i++) {
            oacc[i][0] *= corr0; oacc[i][1] *= corr0;
            oacc[i][2] *= corr1; oacc[i][3] *= corr1;
        }
        // stage P
        #pragma unroll
        for (int nf = 0; nf < 8; nf++) {
            int col = nf * 8 + 2 * t;
            Ps[w][g][col]         = f2tf(s[nf][0]);
            Ps[w][g][col + 1]     = f2tf(s[nf][1]);
            Ps[w][g + 8][col]     = f2tf(s[nf][2]);
            Ps[w][g + 8][col + 1] = f2tf(s[nf][3]);
        }
        __syncwarp();
        // O += P V
        #pragma unroll
        for (int ks2 = 0; ks2 < 8; ks2++) {
            int kk = ks2 * 8;
            unsigned a0 = Ps[w][g][kk + t];
            unsigned a1 = Ps[w][g + 8][kk + t];
            unsigned a2 = Ps[w][g][kk + t + 4];
            unsigned a3 = Ps[w][g + 8][kk + t + 4];
            #pragma unroll
            for (int nf2 = 0; nf2 < 4; nf2++) {
                unsigned b0 = Vs[kk + t][nf2 * 8 + g];
                unsigned b1 = Vs[kk + t + 4][nf2 * 8 + g];
                mma_tf32(oacc[nf2], a0, a1, a2, a3, b0, b1);
            }
        }
    }
    // output
    float inv0 = 1.f / lrow[0], inv1 = 1.f / lrow[1];
    #pragma unroll
    for (int nf2 = 0; nf2 < 4; nf2++) {
        int feat = nf2 * 8 + 2 * t;
        if (r0g < Tt)
            *(float2*)(out + ((size_t)(b * Tt + r0g)) * 256 + h * 32 + feat) =
                make_float2(oacc[nf2][0] * inv0, oacc[nf2][1] * inv0);
        if (r1g < Tt)
            *(float2*)(out + ((size_t)(b * Tt + r1g)) * 256 + h * 32 + feat) =
                make_float2(oacc[nf2][2] * inv1, oacc[nf2][3] * inv1);
    }
}

__global__ void copy_kernel(float* __restrict__ out) {
    int i = blockIdx.x * 256 + threadIdx.x;
    if (i < Mrows * Dd) out[i] = g_x[i];
}

// ---------------------------------------------------------------------------
extern "C" void kernel_launch(void* const* d_in, const int* in_sizes, int n_in,
                              void* d_out, int out_size) {
    const float* nf       = (const float*)d_in[0];
    const int*   adj      = (const int*)  d_in[1];
    const float* dist     = (const float*)d_in[2];
    const float* eoh      = (const float*)d_in[3];
    const float* npw      = (const float*)d_in[4];
    const float* npb      = (const float*)d_in[5];
    const float* cls      = (const float*)d_in[6];
    const float* etw      = (const float*)d_in[7];
    const float* noedge   = (const float*)d_in[8];
    const float* degscale = (const float*)d_in[9];
    const float* gamma    = (const float*)d_in[10];
    const float* v2n      = (const float*)d_in[11];
    const float* n2v      = (const float*)d_in[12];
    const float* vself    = (const float*)d_in[13];
    const float* ln1g = (const float*)d_in[14]; const float* ln1b = (const float*)d_in[15];
    const float* qw   = (const float*)d_in[16]; const float* qb   = (const float*)d_in[17];
    const float* kw   = (const float*)d_in[18]; const float* kb   = (const float*)d_in[19];
    const float* vw   = (const float*)d_in[20]; const float* vb   = (const float*)d_in[21];
    const float* ow   = (const float*)d_in[22]; const float* ob   = (const float*)d_in[23];
    const float* ln2g = (const float*)d_in[24]; const float* ln2b = (const float*)d_in[25];
    const float* fc1w = (const float*)d_in[26]; const float* fc1b = (const float*)d_in[27];
    const float* fc2w = (const float*)d_in[28]; const float* fc2b = (const float*)d_in[29];

    float *p_x, *p_xn, *p_q, *p_k, *p_v, *p_att, *p_m1, *p_bias;
    cudaGetSymbolAddress((void**)&p_x,    g_x);
    cudaGetSymbolAddress((void**)&p_xn,   g_xn);
    cudaGetSymbolAddress((void**)&p_q,    g_q);
    cudaGetSymbolAddress((void**)&p_k,    g_k);
    cudaGetSymbolAddress((void**)&p_v,    g_v);
    cudaGetSymbolAddress((void**)&p_att,  g_att);
    cudaGetSymbolAddress((void**)&p_m1,   g_m1);
    cudaGetSymbolAddress((void**)&p_bias, g_bias);

    deg_kernel<<<(Bq * Nn) / 8, 256>>>(adj);
    degmax_kernel<<<Bq, 256>>>();
    bias_edge_kernel<<<dim3(Nn, Bq), 256>>>(adj, dist, eoh, etw, noedge, degscale, gamma);
    bias_fill_kernel<<<Bq, 256>>>(v2n, n2v, vself);

    proj_kernel<<<dim3(Tt, Bq), 256>>>(nf, npw, npb, cls);

    dim3 ggrid(4, (Mrows + 63) / 64);  // (4, 97)
    dim3 agrid(Bq * Hh, (Tt + 63) / 64);  // (64, 13)
    for (int l = 0; l < Ll; l++) {
        size_t wo = (size_t)l * Dd * Dd;
        size_t bo = (size_t)l * Dd;
        ln_kernel<<<Mrows / 8, 256>>>(p_x, ln1g + bo, ln1b + bo, p_xn);
        gemm_tc<0><<<ggrid, 128>>>(p_xn, qw + wo, qb + bo, p_q);
        gemm_tc<0><<<ggrid, 128>>>(p_xn, kw + wo, kb + bo, p_k);
        gemm_tc<0><<<ggrid, 128>>>(p_xn, vw + wo, vb + bo, p_v);
        attn_tc<<<agrid, 128>>>(p_q, p_k, p_v, p_bias, p_att);
        gemm_tc<2><<<ggrid, 128>>>(p_att, ow + wo, ob + bo, p_x);
        ln_kernel<<<Mrows / 8, 256>>>(p_x, ln2g + bo, ln2b + bo, p_xn);
        gemm_tc<1><<<ggrid, 128>>>(p_xn, fc1w + wo, fc1b + bo, p_m1);
        gemm_tc<2><<<ggrid, 128>>>(p_m1, fc2w + wo, fc2b + bo, p_x);
    }
    copy_kernel<<<(Mrows * Dd + 255) / 256, 256>>>((float*)d_out);
}

// round 4
// speedup vs baseline: 3.4726x; 1.2856x over previous
#include <cuda_runtime.h>
#include <math.h>

// Problem constants
#define Bq 8
#define Nn 768
#define Tt 769
#define Dd 256
#define Hh 8
#define Ll 6
#define Ff 128
#define Mrows (Bq*Tt)   // 6152

// ---- scratch (device globals; no allocation allowed) ----
__device__ float g_bias[Bq*Tt*Tt];
__device__ float g_x  [Mrows*Dd];
__device__ float g_xn [Mrows*Dd];
__device__ float g_q  [Mrows*Dd];
__device__ float g_k  [Mrows*Dd];
__device__ float g_v  [Mrows*Dd];
__device__ float g_att[Mrows*Dd];
__device__ float g_m1 [Mrows*Dd];
__device__ float g_deg[Bq*Nn];
__device__ float g_degmax[Bq];

// ---------------------------------------------------------------------------
__device__ __forceinline__ unsigned f2tf(float x) {
    unsigned u; asm("cvt.rna.tf32.f32 %0, %1;" : "=r"(u) : "f"(x)); return u;
}
__device__ __forceinline__ void mma_tf32(float* d,
                                         unsigned a0, unsigned a1, unsigned a2, unsigned a3,
                                         unsigned b0, unsigned b1) {
    asm volatile("mma.sync.aligned.m16n8k8.row.col.f32.tf32.tf32.f32 "
                 "{%0,%1,%2,%3}, {%4,%5,%6,%7}, {%8,%9}, {%0,%1,%2,%3};\n"
                 : "+f"(d[0]), "+f"(d[1]), "+f"(d[2]), "+f"(d[3])
                 : "r"(a0), "r"(a1), "r"(a2), "r"(a3), "r"(b0), "r"(b1));
}
__device__ __forceinline__ void cpa16(float* dst, const float* src, bool pred) {
    unsigned d = (unsigned)__cvta_generic_to_shared(dst);
    int sz = pred ? 16 : 0;
    asm volatile("cp.async.ca.shared.global [%0], [%1], 16, %2;\n"
                 :: "r"(d), "l"(src), "r"(sz));
}
#define CP_COMMIT() asm volatile("cp.async.commit_group;\n")
#define CP_WAIT1()  asm volatile("cp.async.wait_group 1;\n")
#define CP_WAIT0()  asm volatile("cp.async.wait_group 0;\n")

// ---------------------------------------------------------------------------
__global__ void deg_kernel(const int* __restrict__ adj) {
    int row  = blockIdx.x * 8 + (threadIdx.x >> 5);
    int lane = threadIdx.x & 31;
    const int* a = adj + (size_t)row * Nn;
    float s = 0.f;
    #pragma unroll
    for (int k2 = 0; k2 < Nn / 32; k2++) s += (float)a[lane + 32 * k2];
    #pragma unroll
    for (int o = 16; o; o >>= 1) s += __shfl_xor_sync(0xffffffffu, s, o);
    if (lane == 0) g_deg[row] = s;
}

__global__ void degmax_kernel() {
    int b = blockIdx.x, tid = threadIdx.x;
    float m = 0.f;
    for (int i = tid; i < Nn; i += 256) m = fmaxf(m, g_deg[b * Nn + i]);
    __shared__ float sm[256];
    sm[tid] = m; __syncthreads();
    for (int s = 128; s; s >>= 1) {
        if (tid < s) sm[tid] = fmaxf(sm[tid], sm[tid + s]);
        __syncthreads();
    }
    if (tid == 0) g_degmax[b] = sm[0];
}

__global__ void bias_edge_kernel(const int* __restrict__ adj,
                                 const float* __restrict__ dist,
                                 const float* __restrict__ eoh,
                                 const float* __restrict__ etw,
                                 const float* __restrict__ noedge,
                                 const float* __restrict__ degscale,
                                 const float* __restrict__ gamma) {
    int i = blockIdx.x, b = blockIdx.y;
    float e0 = etw[0], e1 = etw[1], e2 = etw[2], e3 = etw[3];
    float ne = noedge[0], ds = degscale[0], ga = gamma[0];
    float di = g_deg[b * Nn + i];
    float inv_dmx = 1.f / (g_degmax[b] + 1e-6f);
    size_t base = ((size_t)b * Nn + i) * Nn;
    for (int j = threadIdx.x; j < Nn; j += 256) {
        const float* eo = eoh + (base + j) * 4;
        float e = eo[0] * e0 + eo[1] * e1 + eo[2] * e2 + eo[3] * e3 - ga * dist[base + j];
        if (adj[base + j] == 0) e += ne;
        e += ds * (di + g_deg[b * Nn + j]) * inv_dmx;
        g_bias[(size_t)b * Tt * Tt + (size_t)(i + 1) * Tt + (j + 1)] = e;
    }
}

__global__ void bias_fill_kernel(const float* v2n, const float* n2v, const float* vself) {
    int b = blockIdx.x;
    float a = v2n[0], c = n2v[0];
    size_t base = (size_t)b * Tt * Tt;
    for (int t = threadIdx.x + 1; t < Tt; t += 256) {
        g_bias[base + t]              = a;
        g_bias[base + (size_t)t * Tt] = c;
    }
    if (threadIdx.x == 0) g_bias[base] = vself[0];
}

// ---------------------------------------------------------------------------
__global__ void proj_kernel(const float* __restrict__ nf, const float* __restrict__ W,
                            const float* __restrict__ bb, const float* __restrict__ cls) {
    int t = blockIdx.x, b = blockIdx.y, tid = threadIdx.x;
    if (t == 0) { g_x[((size_t)b * Tt) * Dd + tid] = cls[tid]; return; }
    __shared__ float sm[Ff];
    if (tid < Ff) sm[tid] = nf[((size_t)b * Nn + (t - 1)) * Ff + tid];
    __syncthreads();
    float a = bb[tid];
    #pragma unroll 8
    for (int k2 = 0; k2 < Ff; k2++) a = fmaf(sm[k2], W[k2 * Dd + tid], a);
    g_x[((size_t)b * Tt + t) * Dd + tid] = a;
}

// ---------------------------------------------------------------------------
__global__ void ln_kernel(const float* __restrict__ x, const float* __restrict__ g,
                          const float* __restrict__ bb, float* __restrict__ xn) {
    int row  = blockIdx.x * 8 + (threadIdx.x >> 5);
    int lane = threadIdx.x & 31;
    const float* xr = x + (size_t)row * Dd;
    float v[8], s = 0.f, s2 = 0.f;
    #pragma unroll
    for (int k2 = 0; k2 < 8; k2++) {
        v[k2] = xr[lane + 32 * k2];
        s += v[k2]; s2 += v[k2] * v[k2];
    }
    #pragma unroll
    for (int o = 16; o; o >>= 1) {
        s  += __shfl_xor_sync(0xffffffffu, s, o);
        s2 += __shfl_xor_sync(0xffffffffu, s2, o);
    }
    float mean = s * (1.f / Dd);
    float var  = s2 * (1.f / Dd) - mean * mean;
    float rs = rsqrtf(var + 1e-5f);
    float* orow = xn + (size_t)row * Dd;
    #pragma unroll
    for (int k2 = 0; k2 < 8; k2++) {
        int d = lane + 32 * k2;
        orow[d] = (v[k2] - mean) * rs * g[d] + bb[d];
    }
}

// ---------------------------------------------------------------------------
// Tensor-core GEMM body (tf32), BM=128 BN=64 BK=32, 256 threads / 8 warps,
// cp.async double-buffered. smem: As [2][128][36], Ws [2][32][68] (raw fp32).
// EPI: 0=store  1=GELU  2=residual add
#define GA_STRIDE 36
#define GW_STRIDE 68
#define GEMM_SMEM ((2*128*GA_STRIDE + 2*32*GW_STRIDE) * 4)

template<int EPI>
__device__ __forceinline__ void gemm_body(float* sm,
                                          const float* __restrict__ A,
                                          const float* __restrict__ W,
                                          const float* __restrict__ bias,
                                          float* __restrict__ C,
                                          int m0, int n0) {
    const int M = Mrows;
    float* As = sm;                    // [2][128][36]
    float* Ws = sm + 2 * 128 * GA_STRIDE;
    int tid = threadIdx.x, w = tid >> 5, lane = tid & 31;
    int g = lane >> 2, t = lane & 3;
    int wm = (w >> 1) * 32, wn = (w & 1) * 32;

    auto issue = [&](int kt, int buf) {
        int k0 = kt * 32;
        float* Ab = As + buf * 128 * GA_STRIDE;
        #pragma unroll
        for (int r = 0; r < 4; r++) {
            int idx = tid + 256 * r;
            int m = idx >> 3, ch = idx & 7;
            bool p = (m0 + m) < M;
            const float* src = A + (size_t)(p ? (m0 + m) : 0) * 256 + k0 + ch * 4;
            cpa16(Ab + m * GA_STRIDE + ch * 4, src, p);
        }
        float* Wb = Ws + buf * 32 * GW_STRIDE;
        #pragma unroll
        for (int r = 0; r < 2; r++) {
            int idx = tid + 256 * r;
            int kk = idx >> 4, ch = idx & 15;
            cpa16(Wb + kk * GW_STRIDE + ch * 4, W + (size_t)(k0 + kk) * 256 + n0 + ch * 4, true);
        }
        CP_COMMIT();
    };

    float acc[2][4][4];
    #pragma unroll
    for (int i = 0; i < 2; i++)
        #pragma unroll
        for (int j = 0; j < 4; j++)
            #pragma unroll
            for (int c = 0; c < 4; c++) acc[i][j][c] = 0.f;

    issue(0, 0);
    for (int kt = 0; kt < 8; kt++) {
        int buf = kt & 1;
        if (kt < 7) { issue(kt + 1, buf ^ 1); CP_WAIT1(); }
        else        { CP_WAIT0(); }
        __syncthreads();
        const float* Ab = As + buf * 128 * GA_STRIDE;
        const float* Wb = Ws + buf * 32 * GW_STRIDE;
        #pragma unroll
        for (int ks = 0; ks < 4; ks++) {
            int kb = ks * 8;
            unsigned a[2][4];
            #pragma unroll
            for (int mf = 0; mf < 2; mf++) {
                int mb = wm + mf * 16;
                a[mf][0] = f2tf(Ab[(mb + g)     * GA_STRIDE + kb + t]);
                a[mf][1] = f2tf(Ab[(mb + g + 8) * GA_STRIDE + kb + t]);
                a[mf][2] = f2tf(Ab[(mb + g)     * GA_STRIDE + kb + t + 4]);
                a[mf][3] = f2tf(Ab[(mb + g + 8) * GA_STRIDE + kb + t + 4]);
            }
            #pragma unroll
            for (int nf = 0; nf < 4; nf++) {
                unsigned b0 = f2tf(Wb[(kb + t)     * GW_STRIDE + wn + nf * 8 + g]);
                unsigned b1 = f2tf(Wb[(kb + t + 4) * GW_STRIDE + wn + nf * 8 + g]);
                #pragma unroll
                for (int mf = 0; mf < 2; mf++)
                    mma_tf32(acc[mf][nf], a[mf][0], a[mf][1], a[mf][2], a[mf][3], b0, b1);
            }
        }
        __syncthreads();
    }
    // epilogue
    #pragma unroll
    for (int mf = 0; mf < 2; mf++) {
        int row0 = m0 + wm + mf * 16 + g;
        #pragma unroll
        for (int nf = 0; nf < 4; nf++) {
            int col = n0 + wn + nf * 8 + 2 * t;
            float bv0 = bias[col], bv1 = bias[col + 1];
            #pragma unroll
            for (int half = 0; half < 2; half++) {
                int row = row0 + half * 8;
                if (row >= M) continue;
                float v0 = acc[mf][nf][half * 2 + 0] + bv0;
                float v1 = acc[mf][nf][half * 2 + 1] + bv1;
                float* cp = C + (size_t)row * 256 + col;
                if (EPI == 1) {
                    v0 = 0.5f * v0 * (1.f + erff(v0 * 0.70710678118654752f));
                    v1 = 0.5f * v1 * (1.f + erff(v1 * 0.70710678118654752f));
                }
                if (EPI == 2) { v0 += cp[0]; v1 += cp[1]; }
                *(float2*)cp = make_float2(v0, v1);
            }
        }
    }
}

template<int EPI>
__global__ void __launch_bounds__(256)
gemm_one(const float* __restrict__ A, const float* __restrict__ W,
         const float* __restrict__ bias, float* __restrict__ C) {
    extern __shared__ float sm[];
    gemm_body<EPI>(sm, A, W, bias, C, blockIdx.y * 128, blockIdx.x * 64);
}

__global__ void __launch_bounds__(256)
gemm_qkv(const float* __restrict__ A,
         const float* w0, const float* bb0, float* c0,
         const float* w1, const float* bb1, float* c1,
         const float* w2, const float* bb2, float* c2) {
    extern __shared__ float sm[];
    int sel = blockIdx.x >> 2;
    int n0 = (blockIdx.x & 3) * 64, m0 = blockIdx.y * 128;
    const float* W  = (sel == 0) ? w0  : (sel == 1) ? w1  : w2;
    const float* bb = (sel == 0) ? bb0 : (sel == 1) ? bb1 : bb2;
    float*       C  = (sel == 0) ? c0  : (sel == 1) ? c1  : c2;
    gemm_body<0>(sm, A, W, bb, C, m0, n0);
}

// ---------------------------------------------------------------------------
// Tensor-core flash attention (tf32), cp.async double-buffered K/V.
// Block = (b,h) x 64-q-row tile, 4 warps (16 q rows each).
#define AQ_STRIDE 36
#define AK_STRIDE 36
#define AV_STRIDE 40
#define AP_STRIDE 68
#define ATTN_SMEM ((64*AQ_STRIDE + 2*64*AK_STRIDE + 2*64*AV_STRIDE + 4*16*AP_STRIDE) * 4)

__global__ void __launch_bounds__(128)
attn_tc(const float* __restrict__ q, const float* __restrict__ k,
        const float* __restrict__ v, const float* __restrict__ bias,
        float* __restrict__ out) {
    extern __shared__ float sm[];
    unsigned* Qs = (unsigned*)sm;                    // [64][36] tf32
    float*    Ks = sm + 64 * AQ_STRIDE;              // [2][64][36] raw
    float*    Vs = Ks + 2 * 64 * AK_STRIDE;          // [2][64][40] raw
    unsigned* Ps = (unsigned*)(Vs + 2 * 64 * AV_STRIDE);  // [4][16][68]

    int b = blockIdx.x >> 3, h = blockIdx.x & 7;
    int q0 = blockIdx.y * 64;
    int tid = threadIdx.x, w = tid >> 5, lane = tid & 31;
    int g = lane >> 2, t = lane & 3;

    const float scale = 0.17677669529663687f;  // 1/sqrt(32)
    const float* kb_ = k + (size_t)b * Tt * Dd + h * 32;
    const float* vb_ = v + (size_t)b * Tt * Dd + h * 32;
    const float* biasb = bias + (size_t)b * Tt * Tt;

    auto issueKV = [&](int jt, int buf) {
        int j0 = jt * 64;
        float* Kb = Ks + buf * 64 * AK_STRIDE;
        float* Vb = Vs + buf * 64 * AV_STRIDE;
        #pragma unroll
        for (int r = 0; r < 4; r++) {
            int idx = tid + 128 * r;
            int key = idx >> 3, ch = idx & 7;
            int gj = j0 + key;
            bool p = gj < Tt;
            size_t off = (size_t)(p ? gj : 0) * 256 + ch * 4;
            cpa16(Kb + key * AK_STRIDE + ch * 4, kb_ + off, p);
            cpa16(Vb + key * AV_STRIDE + ch * 4, vb_ + off, p);
        }
        CP_COMMIT();
    };

    // stage Q (scaled, tf32 bits)
    #pragma unroll
    for (int r = 0; r < 4; r++) {
        int idx = tid + 128 * r;
        int m = idx >> 3, k4 = (idx & 7) << 2;
        float4 qv = make_float4(0.f, 0.f, 0.f, 0.f);
        int qr = q0 + m;
        if (qr < Tt) qv = *(const float4*)(q + ((size_t)(b * Tt + qr)) * 256 + h * 32 + k4);
        Qs[m * AQ_STRIDE + k4 + 0] = f2tf(qv.x * scale);
        Qs[m * AQ_STRIDE + k4 + 1] = f2tf(qv.y * scale);
        Qs[m * AQ_STRIDE + k4 + 2] = f2tf(qv.z * scale);
        Qs[m * AQ_STRIDE + k4 + 3] = f2tf(qv.w * scale);
    }
    issueKV(0, 0);
    __syncthreads();
    int mb = w * 16;
    unsigned qa[4][4];
    #pragma unroll
    for (int ks = 0; ks < 4; ks++) {
        int kb2 = ks * 8;
        qa[ks][0] = Qs[(mb + g)     * AQ_STRIDE + kb2 + t];
        qa[ks][1] = Qs[(mb + g + 8) * AQ_STRIDE + kb2 + t];
        qa[ks][2] = Qs[(mb + g)     * AQ_STRIDE + kb2 + t + 4];
        qa[ks][3] = Qs[(mb + g + 8) * AQ_STRIDE + kb2 + t + 4];
    }

    float mrow[2] = {-1e30f, -1e30f}, lrow[2] = {0.f, 0.f};
    float oacc[4][4];
    #pragma unroll
    for (int i = 0; i < 4; i++)
        #pragma unroll
        for (int c = 0; c < 4; c++) oacc[i][c] = 0.f;

    int r0g = q0 + mb + g, r1g = r0g + 8;
    const int NTILES = (Tt + 63) / 64;  // 13

    for (int jt = 0; jt < NTILES; jt++) {
        int buf = jt & 1;
        int j0 = jt * 64;

        // scalar bias loads (bias row stride 769 is odd -> no vector loads!)
        // issued before the cp.async wait so L2 latency overlaps the pipeline
        float s[8][4];
        #pragma unroll
        for (int nf = 0; nf < 8; nf++) {
            int col = j0 + nf * 8 + 2 * t;
            bool cok0 = col < Tt, cok1 = (col + 1) < Tt;
            s[nf][0] = (r0g < Tt && cok0) ? __ldg(biasb + (size_t)r0g * Tt + col)     : -1e30f;
            s[nf][1] = (r0g < Tt && cok1) ? __ldg(biasb + (size_t)r0g * Tt + col + 1) : -1e30f;
            s[nf][2] = (r1g < Tt && cok0) ? __ldg(biasb + (size_t)r1g * Tt + col)     : -1e30f;
            s[nf][3] = (r1g < Tt && cok1) ? __ldg(biasb + (size_t)r1g * Tt + col + 1) : -1e30f;
        }

        if (jt + 1 < NTILES) { issueKV(jt + 1, buf ^ 1); CP_WAIT1(); }
        else                 { CP_WAIT0(); }
        __syncthreads();

        const float* Kb = Ks + buf * 64 * AK_STRIDE;
        const float* Vb = Vs + buf * 64 * AV_STRIDE;

        // S += Q K^T
        #pragma unroll
        for (int ks = 0; ks < 4; ks++) {
            int kb2 = ks * 8;
            #pragma unroll
            for (int nf = 0; nf < 8; nf++) {
                unsigned b0 = f2tf(Kb[(nf * 8 + g) * AK_STRIDE + kb2 + t]);
                unsigned b1 = f2tf(Kb[(nf * 8 + g) * AK_STRIDE + kb2 + t + 4]);
                mma_tf32(s[nf], qa[ks][0], qa[ks][1], qa[ks][2], qa[ks][3], b0, b1);
            }
        }
        // online softmax (rows g, g+8); quad-wide reductions
        float tmax[2] = {-1e30f, -1e30f};
        #pragma unroll
        for (int nf = 0; nf < 8; nf++) {
            tmax[0] = fmaxf(tmax[0], fmaxf(s[nf][0], s[nf][1]));
            tmax[1] = fmaxf(tmax[1], fmaxf(s[nf][2], s[nf][3]));
        }
        #pragma unroll
        for (int o = 1; o <= 2; o <<= 1) {
            tmax[0] = fmaxf(tmax[0], __shfl_xor_sync(0xffffffffu, tmax[0], o));
            tmax[1] = fmaxf(tmax[1], __shfl_xor_sync(0xffffffffu, tmax[1], o));
        }
        float mn0 = fmaxf(mrow[0], tmax[0]), mn1 = fmaxf(mrow[1], tmax[1]);
        float corr0 = __expf(mrow[0] - mn0), corr1 = __expf(mrow[1] - mn1);
        mrow[0] = mn0; mrow[1] = mn1;
        float sum0 = 0.f, sum1 = 0.f;
        #pragma unroll
        for (int nf = 0; nf < 8; nf++) {
            s[nf][0] = __expf(s[nf][0] - mn0); sum0 += s[nf][0];
            s[nf][1] = __expf(s[nf][1] - mn0); sum0 += s[nf][1];
            s[nf][2] = __expf(s[nf][2] - mn1); sum1 += s[nf][2];
            s[nf][3] = __expf(s[nf][3] - mn1); sum1 += s[nf][3];
        }
        #pragma unroll
        for (int o = 1; o <= 2; o <<= 1) {
            sum0 += __shfl_xor_sync(0xffffffffu, sum0, o);
            sum1 += __shfl_xor_sync(0xffffffffu, sum1, o);
        }
        lrow[0] = lrow[0] * corr0 + sum0;
        lrow[1] = lrow[1] * corr1 + sum1;
        #pragma unroll
        for (int i = 0; i < 4; i++) {
            oacc[i][0] *= corr0; oacc[i][1] *= corr0;
            oacc[i][2] *= corr1; oacc[i][3] *= corr1;
        }
        // stage P (per-warp)
        unsigned* Pw = Ps + w * 16 * AP_STRIDE;
        #pragma unroll
        for (int nf = 0; nf < 8; nf++) {
            int col = nf * 8 + 2 * t;
            Pw[g * AP_STRIDE + col]           = f2tf(s[nf][0]);
            Pw[g * AP_STRIDE + col + 1]       = f2tf(s[nf][1]);
            Pw[(g + 8) * AP_STRIDE + col]     = f2tf(s[nf][2]);
            Pw[(g + 8) * AP_STRIDE + col + 1] = f2tf(s[nf][3]);
        }
        __syncwarp();
        // O += P V
        #pragma unroll
        for (int ks2 = 0; ks2 < 8; ks2++) {
            int kk = ks2 * 8;
            unsigned a0 = Pw[g * AP_STRIDE + kk + t];
            unsigned a1 = Pw[(g + 8) * AP_STRIDE + kk + t];
            unsigned a2 = Pw[g * AP_STRIDE + kk + t + 4];
            unsigned a3 = Pw[(g + 8) * AP_STRIDE + kk + t + 4];
            #pragma unroll
            for (int nf2 = 0; nf2 < 4; nf2++) {
                unsigned b0 = f2tf(Vb[(kk + t)     * AV_STRIDE + nf2 * 8 + g]);
                unsigned b1 = f2tf(Vb[(kk + t + 4) * AV_STRIDE + nf2 * 8 + g]);
                mma_tf32(oacc[nf2], a0, a1, a2, a3, b0, b1);
            }
        }
        __syncthreads();
    }
    // output
    float inv0 = 1.f / lrow[0], inv1 = 1.f / lrow[1];
    #pragma unroll
    for (int nf2 = 0; nf2 < 4; nf2++) {
        int feat = nf2 * 8 + 2 * t;
        if (r0g < Tt)
            *(float2*)(out + ((size_t)(b * Tt + r0g)) * 256 + h * 32 + feat) =
                make_float2(oacc[nf2][0] * inv0, oacc[nf2][1] * inv0);
        if (r1g < Tt)
            *(float2*)(out + ((size_t)(b * Tt + r1g)) * 256 + h * 32 + feat) =
                make_float2(oacc[nf2][2] * inv1, oacc[nf2][3] * inv1);
    }
}

__global__ void copy_kernel(float* __restrict__ out) {
    int i = blockIdx.x * 256 + threadIdx.x;
    if (i < Mrows * Dd) out[i] = g_x[i];
}

// ---------------------------------------------------------------------------
extern "C" void kernel_launch(void* const* d_in, const int* in_sizes, int n_in,
                              void* d_out, int out_size) {
    const float* nf       = (const float*)d_in[0];
    const int*   adj      = (const int*)  d_in[1];
    const float* dist     = (const float*)d_in[2];
    const float* eoh      = (const float*)d_in[3];
    const float* npw      = (const float*)d_in[4];
    const float* npb      = (const float*)d_in[5];
    const float* cls      = (const float*)d_in[6];
    const float* etw      = (const float*)d_in[7];
    const float* noedge   = (const float*)d_in[8];
    const float* degscale = (const float*)d_in[9];
    const float* gamma    = (const float*)d_in[10];
    const float* v2n      = (const float*)d_in[11];
    const float* n2v      = (const float*)d_in[12];
    const float* vself    = (const float*)d_in[13];
    const float* ln1g = (const float*)d_in[14]; const float* ln1b = (const float*)d_in[15];
    const float* qw   = (const float*)d_in[16]; const float* qb   = (const float*)d_in[17];
    const float* kw   = (const float*)d_in[18]; const float* kb   = (const float*)d_in[19];
    const float* vw   = (const float*)d_in[20]; const float* vb   = (const float*)d_in[21];
    const float* ow   = (const float*)d_in[22]; const float* ob   = (const float*)d_in[23];
    const float* ln2g = (const float*)d_in[24]; const float* ln2b = (const float*)d_in[25];
    const float* fc1w = (const float*)d_in[26]; const float* fc1b = (const float*)d_in[27];
    const float* fc2w = (const float*)d_in[28]; const float* fc2b = (const float*)d_in[29];

    float *p_x, *p_xn, *p_q, *p_k, *p_v, *p_att, *p_m1, *p_bias;
    cudaGetSymbolAddress((void**)&p_x,    g_x);
    cudaGetSymbolAddress((void**)&p_xn,   g_xn);
    cudaGetSymbolAddress((void**)&p_q,    g_q);
    cudaGetSymbolAddress((void**)&p_k,    g_k);
    cudaGetSymbolAddress((void**)&p_v,    g_v);
    cudaGetSymbolAddress((void**)&p_att,  g_att);
    cudaGetSymbolAddress((void**)&p_m1,   g_m1);
    cudaGetSymbolAddress((void**)&p_bias, g_bias);

    cudaFuncSetAttribute(gemm_qkv,    cudaFuncAttributeMaxDynamicSharedMemorySize, GEMM_SMEM);
    cudaFuncSetAttribute(gemm_one<1>, cudaFuncAttributeMaxDynamicSharedMemorySize, GEMM_SMEM);
    cudaFuncSetAttribute(gemm_one<2>, cudaFuncAttributeMaxDynamicSharedMemorySize, GEMM_SMEM);
    cudaFuncSetAttribute(attn_tc,     cudaFuncAttributeMaxDynamicSharedMemorySize, ATTN_SMEM);

    deg_kernel<<<(Bq * Nn) / 8, 256>>>(adj);
    degmax_kernel<<<Bq, 256>>>();
    bias_edge_kernel<<<dim3(Nn, Bq), 256>>>(adj, dist, eoh, etw, noedge, degscale, gamma);
    bias_fill_kernel<<<Bq, 256>>>(v2n, n2v, vself);

    proj_kernel<<<dim3(Tt, Bq), 256>>>(nf, npw, npb, cls);

    dim3 ggrid (4,  (Mrows + 127) / 128);   // (4, 49)
    dim3 qgrid (12, (Mrows + 127) / 128);   // (12, 49)
    dim3 agrid (Bq * Hh, (Tt + 63) / 64);   // (64, 13)
    for (int l = 0; l < Ll; l++) {
        size_t wo = (size_t)l * Dd * Dd;
        size_t bo = (size_t)l * Dd;
        ln_kernel<<<Mrows / 8, 256>>>(p_x, ln1g + bo, ln1b + bo, p_xn);
        gemm_qkv<<<qgrid, 256, GEMM_SMEM>>>(p_xn, qw + wo, qb + bo, p_q,
                                            kw + wo, kb + bo, p_k,
                                            vw + wo, vb + bo, p_v);
        attn_tc<<<agrid, 128, ATTN_SMEM>>>(p_q, p_k, p_v, p_bias, p_att);
        gemm_one<2><<<ggrid, 256, GEMM_SMEM>>>(p_att, ow + wo, ob + bo, p_x);
        ln_kernel<<<Mrows / 8, 256>>>(p_x, ln2g + bo, ln2b + bo, p_xn);
        gemm_one<1><<<ggrid, 256, GEMM_SMEM>>>(p_xn, fc1w + wo, fc1b + bo, p_m1);
        gemm_one<2><<<ggrid, 256, GEMM_SMEM>>>(p_m1, fc2w + wo, fc2b + bo, p_x);
    }
    copy_kernel<<<(Mrows * Dd + 255) / 256, 256>>>((float*)d_out);
}

// round 5
// speedup vs baseline: 3.8905x; 1.1203x over previous
#include <cuda_runtime.h>
#include <math.h>

#define Bq 8
#define Nn 768
#define Tt 769
#define Dd 256
#define Hh 8
#define Ll 6
#define Ff 128
#define Mrows (Bq*Tt)   // 6152

__device__ float g_bias[Bq*Tt*Tt];
__device__ float g_x  [Mrows*Dd];
__device__ float g_xn [Mrows*Dd];
__device__ float g_q  [Mrows*Dd];
__device__ float g_k  [Mrows*Dd];
__device__ float g_v  [Mrows*Dd];
__device__ float g_att[Mrows*Dd];
__device__ float g_m1 [Mrows*Dd];
__device__ float g_deg[Bq*Nn];
__device__ float g_degmax[Bq];

// ---------------------------------------------------------------------------
__device__ __forceinline__ unsigned f2tf(float x) {
    unsigned u; asm("cvt.rna.tf32.f32 %0, %1;" : "=r"(u) : "f"(x)); return u;
}
// raw fp32 bits fed to tf32 mma: HW truncates mantissa (RZ). Saves inner-loop cvt.
__device__ __forceinline__ void mma_tf32(float* d,
                                         unsigned a0, unsigned a1, unsigned a2, unsigned a3,
                                         unsigned b0, unsigned b1) {
    asm volatile("mma.sync.aligned.m16n8k8.row.col.f32.tf32.tf32.f32 "
                 "{%0,%1,%2,%3}, {%4,%5,%6,%7}, {%8,%9}, {%0,%1,%2,%3};\n"
                 : "+f"(d[0]), "+f"(d[1]), "+f"(d[2]), "+f"(d[3])
                 : "r"(a0), "r"(a1), "r"(a2), "r"(a3), "r"(b0), "r"(b1));
}
__device__ __forceinline__ void cpa16(float* dst, const float* src, bool pred) {
    unsigned d = (unsigned)__cvta_generic_to_shared(dst);
    int sz = pred ? 16 : 0;
    asm volatile("cp.async.ca.shared.global [%0], [%1], 16, %2;\n"
                 :: "r"(d), "l"(src), "r"(sz));
}
#define CP_COMMIT() asm volatile("cp.async.commit_group;\n")
#define CP_WAIT1()  asm volatile("cp.async.wait_group 1;\n")
#define CP_WAIT0()  asm volatile("cp.async.wait_group 0;\n")

// ---------------------------------------------------------------------------
__global__ void deg_kernel(const int* __restrict__ adj) {
    int row  = blockIdx.x * 8 + (threadIdx.x >> 5);
    int lane = threadIdx.x & 31;
    const int* a = adj + (size_t)row * Nn;
    float s = 0.f;
    #pragma unroll
    for (int k2 = 0; k2 < Nn / 32; k2++) s += (float)a[lane + 32 * k2];
    #pragma unroll
    for (int o = 16; o; o >>= 1) s += __shfl_xor_sync(0xffffffffu, s, o);
    if (lane == 0) g_deg[row] = s;
}

__global__ void degmax_kernel() {
    int b = blockIdx.x, tid = threadIdx.x;
    float m = 0.f;
    for (int i = tid; i < Nn; i += 256) m = fmaxf(m, g_deg[b * Nn + i]);
    __shared__ float sm[256];
    sm[tid] = m; __syncthreads();
    for (int s = 128; s; s >>= 1) {
        if (tid < s) sm[tid] = fmaxf(sm[tid], sm[tid + s]);
        __syncthreads();
    }
    if (tid == 0) g_degmax[b] = sm[0];
}

__global__ void bias_edge_kernel(const int* __restrict__ adj,
                                 const float* __restrict__ dist,
                                 const float* __restrict__ eoh,
                                 const float* __restrict__ etw,
                                 const float* __restrict__ noedge,
                                 const float* __restrict__ degscale,
                                 const float* __restrict__ gamma) {
    int i = blockIdx.x, b = blockIdx.y;
    float e0 = etw[0], e1 = etw[1], e2 = etw[2], e3 = etw[3];
    float ne = noedge[0], ds = degscale[0], ga = gamma[0];
    float di = g_deg[b * Nn + i];
    float inv_dmx = 1.f / (g_degmax[b] + 1e-6f);
    size_t base = ((size_t)b * Nn + i) * Nn;
    for (int j = threadIdx.x; j < Nn; j += 256) {
        const float* eo = eoh + (base + j) * 4;
        float e = eo[0] * e0 + eo[1] * e1 + eo[2] * e2 + eo[3] * e3 - ga * dist[base + j];
        if (adj[base + j] == 0) e += ne;
        e += ds * (di + g_deg[b * Nn + j]) * inv_dmx;
        g_bias[(size_t)b * Tt * Tt + (size_t)(i + 1) * Tt + (j + 1)] = e;
    }
}

__global__ void bias_fill_kernel(const float* v2n, const float* n2v, const float* vself) {
    int b = blockIdx.x;
    float a = v2n[0], c = n2v[0];
    size_t base = (size_t)b * Tt * Tt;
    for (int t = threadIdx.x + 1; t < Tt; t += 256) {
        g_bias[base + t]              = a;
        g_bias[base + (size_t)t * Tt] = c;
    }
    if (threadIdx.x == 0) g_bias[base] = vself[0];
}

// ---------------------------------------------------------------------------
__global__ void proj_kernel(const float* __restrict__ nf, const float* __restrict__ W,
                            const float* __restrict__ bb, const float* __restrict__ cls) {
    int t = blockIdx.x, b = blockIdx.y, tid = threadIdx.x;
    if (t == 0) { g_x[((size_t)b * Tt) * Dd + tid] = cls[tid]; return; }
    __shared__ float sm[Ff];
    if (tid < Ff) sm[tid] = nf[((size_t)b * Nn + (t - 1)) * Ff + tid];
    __syncthreads();
    float a = bb[tid];
    #pragma unroll 8
    for (int k2 = 0; k2 < Ff; k2++) a = fmaf(sm[k2], W[k2 * Dd + tid], a);
    g_x[((size_t)b * Tt + t) * Dd + tid] = a;
}

// ---------------------------------------------------------------------------
__global__ void ln_kernel(const float* __restrict__ x, const float* __restrict__ g,
                          const float* __restrict__ bb, float* __restrict__ xn) {
    int row  = blockIdx.x * 8 + (threadIdx.x >> 5);
    int lane = threadIdx.x & 31;
    const float* xr = x + (size_t)row * Dd;
    float v[8], s = 0.f, s2 = 0.f;
    #pragma unroll
    for (int k2 = 0; k2 < 8; k2++) {
        v[k2] = xr[lane + 32 * k2];
        s += v[k2]; s2 += v[k2] * v[k2];
    }
    #pragma unroll
    for (int o = 16; o; o >>= 1) {
        s  += __shfl_xor_sync(0xffffffffu, s, o);
        s2 += __shfl_xor_sync(0xffffffffu, s2, o);
    }
    float mean = s * (1.f / Dd);
    float var  = s2 * (1.f / Dd) - mean * mean;
    float rs = rsqrtf(var + 1e-5f);
    float* orow = xn + (size_t)row * Dd;
    #pragma unroll
    for (int k2 = 0; k2 < 8; k2++) {
        int d = lane + 32 * k2;
        orow[d] = (v[k2] - mean) * rs * g[d] + bb[d];
    }
}

// ---------------------------------------------------------------------------
// Tensor-core GEMM (tf32 via raw fp32 bits), BM=128 BN=128 BK=32, 256 threads
// 8 warps (4x2), warp tile 32x64. cp.async double-buffered.
// EPI: 0=store  1=GELU  2=residual add
#define GA_STRIDE 36
#define GW_STRIDE 136
#define GEMM_SMEM ((2*128*GA_STRIDE + 2*32*GW_STRIDE) * 4)

template<int EPI>
__device__ __forceinline__ void gemm_body(float* sm,
                                          const float* __restrict__ A,
                                          const float* __restrict__ W,
                                          const float* __restrict__ bias,
                                          float* __restrict__ C,
                                          int m0, int n0) {
    const int M = Mrows;
    float* As = sm;                         // [2][128][36]
    float* Ws = sm + 2 * 128 * GA_STRIDE;   // [2][32][136]
    int tid = threadIdx.x, w = tid >> 5, lane = tid & 31;
    int g = lane >> 2, t = lane & 3;
    int wm = (w >> 1) * 32, wn = (w & 1) * 64;

    auto issue = [&](int kt, int buf) {
        int k0 = kt * 32;
        float* Ab = As + buf * 128 * GA_STRIDE;
        #pragma unroll
        for (int r = 0; r < 4; r++) {
            int idx = tid + 256 * r;
            int m = idx >> 3, ch = idx & 7;
            bool p = (m0 + m) < M;
            const float* src = A + (size_t)(p ? (m0 + m) : 0) * 256 + k0 + ch * 4;
            cpa16(Ab + m * GA_STRIDE + ch * 4, src, p);
        }
        float* Wb = Ws + buf * 32 * GW_STRIDE;
        #pragma unroll
        for (int r = 0; r < 4; r++) {
            int idx = tid + 256 * r;
            int kk = idx >> 5, ch = idx & 31;
            cpa16(Wb + kk * GW_STRIDE + ch * 4, W + (size_t)(k0 + kk) * 256 + n0 + ch * 4, true);
        }
        CP_COMMIT();
    };

    float acc[2][8][4];
    #pragma unroll
    for (int i = 0; i < 2; i++)
        #pragma unroll
        for (int j = 0; j < 8; j++)
            #pragma unroll
            for (int c = 0; c < 4; c++) acc[i][j][c] = 0.f;

    issue(0, 0);
    for (int kt = 0; kt < 8; kt++) {
        int buf = kt & 1;
        if (kt < 7) { issue(kt + 1, buf ^ 1); CP_WAIT1(); }
        else        { CP_WAIT0(); }
        __syncthreads();
        const unsigned* Ab = (const unsigned*)(As + buf * 128 * GA_STRIDE);
        const unsigned* Wb = (const unsigned*)(Ws + buf * 32 * GW_STRIDE);
        #pragma unroll
        for (int ks = 0; ks < 4; ks++) {
            int kb = ks * 8;
            unsigned a[2][4];
            #pragma unroll
            for (int mf = 0; mf < 2; mf++) {
                int mb = wm + mf * 16;
                a[mf][0] = Ab[(mb + g)     * GA_STRIDE + kb + t];
                a[mf][1] = Ab[(mb + g + 8) * GA_STRIDE + kb + t];
                a[mf][2] = Ab[(mb + g)     * GA_STRIDE + kb + t + 4];
                a[mf][3] = Ab[(mb + g + 8) * GA_STRIDE + kb + t + 4];
            }
            #pragma unroll
            for (int nf = 0; nf < 8; nf++) {
                unsigned b0 = Wb[(kb + t)     * GW_STRIDE + wn + nf * 8 + g];
                unsigned b1 = Wb[(kb + t + 4) * GW_STRIDE + wn + nf * 8 + g];
                #pragma unroll
                for (int mf = 0; mf < 2; mf++)
                    mma_tf32(acc[mf][nf], a[mf][0], a[mf][1], a[mf][2], a[mf][3], b0, b1);
            }
        }
        __syncthreads();
    }
    #pragma unroll
    for (int mf = 0; mf < 2; mf++) {
        int row0 = m0 + wm + mf * 16 + g;
        #pragma unroll
        for (int nf = 0; nf < 8; nf++) {
            int col = n0 + wn + nf * 8 + 2 * t;
            float bv0 = bias[col], bv1 = bias[col + 1];
            #pragma unroll
            for (int half = 0; half < 2; half++) {
                int row = row0 + half * 8;
                if (row >= M) continue;
                float v0 = acc[mf][nf][half * 2 + 0] + bv0;
                float v1 = acc[mf][nf][half * 2 + 1] + bv1;
                float* cp = C + (size_t)row * 256 + col;
                if (EPI == 1) {
                    v0 = 0.5f * v0 * (1.f + erff(v0 * 0.70710678118654752f));
                    v1 = 0.5f * v1 * (1.f + erff(v1 * 0.70710678118654752f));
                }
                if (EPI == 2) { v0 += cp[0]; v1 += cp[1]; }
                *(float2*)cp = make_float2(v0, v1);
            }
        }
    }
}

template<int EPI>
__global__ void __launch_bounds__(256)
gemm_one(const float* __restrict__ A, const float* __restrict__ W,
         const float* __restrict__ bias, float* __restrict__ C) {
    extern __shared__ float sm[];
    gemm_body<EPI>(sm, A, W, bias, C, blockIdx.y * 128, blockIdx.x * 128);
}

__global__ void __launch_bounds__(256)
gemm_qkv(const float* __restrict__ A,
         const float* w0, const float* bb0, float* c0,
         const float* w1, const float* bb1, float* c1,
         const float* w2, const float* bb2, float* c2) {
    extern __shared__ float sm[];
    int sel = blockIdx.x >> 1;
    int n0 = (blockIdx.x & 1) * 128, m0 = blockIdx.y * 128;
    const float* W  = (sel == 0) ? w0  : (sel == 1) ? w1  : w2;
    const float* bb = (sel == 0) ? bb0 : (sel == 1) ? bb1 : bb2;
    float*       C  = (sel == 0) ? c0  : (sel == 1) ? c1  : c2;
    gemm_body<0>(sm, A, W, bb, C, m0, n0);
}

// ---------------------------------------------------------------------------
// Flash attention (tf32 raw-bits), 256 threads / 8 warps, 128 q rows per block,
// cp.async double-buffered 64-key K/V tiles.
#define AQ_STRIDE 36
#define AK_STRIDE 36
#define AV_STRIDE 40
#define AP_STRIDE 68
#define ATTN_SMEM ((128*AQ_STRIDE + 2*64*AK_STRIDE + 2*64*AV_STRIDE + 8*16*AP_STRIDE) * 4)

__global__ void __launch_bounds__(256)
attn_tc(const float* __restrict__ q, const float* __restrict__ k,
        const float* __restrict__ v, const float* __restrict__ bias,
        float* __restrict__ out) {
    extern __shared__ float sm[];
    unsigned* Qs = (unsigned*)sm;                         // [128][36] tf32 bits
    float*    Ks = sm + 128 * AQ_STRIDE;                  // [2][64][36]
    float*    Vs = Ks + 2 * 64 * AK_STRIDE;               // [2][64][40]
    float*    Ps = Vs + 2 * 64 * AV_STRIDE;               // [8][16][68]

    int b = blockIdx.x >> 3, h = blockIdx.x & 7;
    int q0 = blockIdx.y * 128;
    int tid = threadIdx.x, w = tid >> 5, lane = tid & 31;
    int g = lane >> 2, t = lane & 3;

    const float scale = 0.17677669529663687f;
    const float* kb_ = k + (size_t)b * Tt * Dd + h * 32;
    const float* vb_ = v + (size_t)b * Tt * Dd + h * 32;
    const float* biasb = bias + (size_t)b * Tt * Tt;

    auto issueKV = [&](int jt, int buf) {
        int j0 = jt * 64;
        float* Kb = Ks + buf * 64 * AK_STRIDE;
        float* Vb = Vs + buf * 64 * AV_STRIDE;
        #pragma unroll
        for (int r = 0; r < 2; r++) {
            int idx = tid + 256 * r;
            int key = idx >> 3, ch = idx & 7;
            int gj = j0 + key;
            bool p = gj < Tt;
            size_t off = (size_t)(p ? gj : 0) * 256 + ch * 4;
            cpa16(Kb + key * AK_STRIDE + ch * 4, kb_ + off, p);
            cpa16(Vb + key * AV_STRIDE + ch * 4, vb_ + off, p);
        }
        CP_COMMIT();
    };

    // stage Q (scaled, rna tf32 — once)
    #pragma unroll
    for (int r = 0; r < 4; r++) {
        int idx = tid + 256 * r;
        int m = idx >> 3, k4 = (idx & 7) << 2;
        float4 qv = make_float4(0.f, 0.f, 0.f, 0.f);
        int qr = q0 + m;
        if (qr < Tt) qv = *(const float4*)(q + ((size_t)(b * Tt + qr)) * 256 + h * 32 + k4);
        Qs[m * AQ_STRIDE + k4 + 0] = f2tf(qv.x * scale);
        Qs[m * AQ_STRIDE + k4 + 1] = f2tf(qv.y * scale);
        Qs[m * AQ_STRIDE + k4 + 2] = f2tf(qv.z * scale);
        Qs[m * AQ_STRIDE + k4 + 3] = f2tf(qv.w * scale);
    }
    issueKV(0, 0);
    __syncthreads();
    int mb = w * 16;
    unsigned qa[4][4];
    #pragma unroll
    for (int ks = 0; ks < 4; ks++) {
        int kb2 = ks * 8;
        qa[ks][0] = Qs[(mb + g)     * AQ_STRIDE + kb2 + t];
        qa[ks][1] = Qs[(mb + g + 8) * AQ_STRIDE + kb2 + t];
        qa[ks][2] = Qs[(mb + g)     * AQ_STRIDE + kb2 + t + 4];
        qa[ks][3] = Qs[(mb + g + 8) * AQ_STRIDE + kb2 + t + 4];
    }

    float mrow[2] = {-1e30f, -1e30f}, lrow[2] = {0.f, 0.f};
    float oacc[4][4];
    #pragma unroll
    for (int i = 0; i < 4; i++)
        #pragma unroll
        for (int c = 0; c < 4; c++) oacc[i][c] = 0.f;

    int r0g = q0 + mb + g, r1g = r0g + 8;
    const int NTILES = (Tt + 63) / 64;  // 13

    for (int jt = 0; jt < NTILES; jt++) {
        int buf = jt & 1;
        int j0 = jt * 64;

        // scalar bias loads (row stride 769 is odd — no vector loads)
        float s[8][4];
        #pragma unroll
        for (int nf = 0; nf < 8; nf++) {
            int col = j0 + nf * 8 + 2 * t;
            bool cok0 = col < Tt, cok1 = (col + 1) < Tt;
            s[nf][0] = (r0g < Tt && cok0) ? __ldg(biasb + (size_t)r0g * Tt + col)     : -1e30f;
            s[nf][1] = (r0g < Tt && cok1) ? __ldg(biasb + (size_t)r0g * Tt + col + 1) : -1e30f;
            s[nf][2] = (r1g < Tt && cok0) ? __ldg(biasb + (size_t)r1g * Tt + col)     : -1e30f;
            s[nf][3] = (r1g < Tt && cok1) ? __ldg(biasb + (size_t)r1g * Tt + col + 1) : -1e30f;
        }

        if (jt + 1 < NTILES) { issueKV(jt + 1, buf ^ 1); CP_WAIT1(); }
        else                 { CP_WAIT0(); }
        __syncthreads();

        const unsigned* Kb = (const unsigned*)(Ks + buf * 64 * AK_STRIDE);
        const unsigned* Vb = (const unsigned*)(Vs + buf * 64 * AV_STRIDE);

        // S += Q K^T
        #pragma unroll
        for (int ks = 0; ks < 4; ks++) {
            int kb2 = ks * 8;
            #pragma unroll
            for (int nf = 0; nf < 8; nf++) {
                unsigned b0 = Kb[(nf * 8 + g) * AK_STRIDE + kb2 + t];
                unsigned b1 = Kb[(nf * 8 + g) * AK_STRIDE + kb2 + t + 4];
                mma_tf32(s[nf], qa[ks][0], qa[ks][1], qa[ks][2], qa[ks][3], b0, b1);
            }
        }
        // online softmax
        float tmax[2] = {-1e30f, -1e30f};
        #pragma unroll
        for (int nf = 0; nf < 8; nf++) {
            tmax[0] = fmaxf(tmax[0], fmaxf(s[nf][0], s[nf][1]));
            tmax[1] = fmaxf(tmax[1], fmaxf(s[nf][2], s[nf][3]));
        }
        #pragma unroll
        for (int o = 1; o <= 2; o <<= 1) {
            tmax[0] = fmaxf(tmax[0], __shfl_xor_sync(0xffffffffu, tmax[0], o));
            tmax[1] = fmaxf(tmax[1], __shfl_xor_sync(0xffffffffu, tmax[1], o));
        }
        float mn0 = fmaxf(mrow[0], tmax[0]), mn1 = fmaxf(mrow[1], tmax[1]);
        float corr0 = __expf(mrow[0] - mn0), corr1 = __expf(mrow[1] - mn1);
        mrow[0] = mn0; mrow[1] = mn1;
        float sum0 = 0.f, sum1 = 0.f;
        #pragma unroll
        for (int nf = 0; nf < 8; nf++) {
            s[nf][0] = __expf(s[nf][0] - mn0); sum0 += s[nf][0];
            s[nf][1] = __expf(s[nf][1] - mn0); sum0 += s[nf][1];
            s[nf][2] = __expf(s[nf][2] - mn1); sum1 += s[nf][2];
            s[nf][3] = __expf(s[nf][3] - mn1); sum1 += s[nf][3];
        }
        #pragma unroll
        for (int o = 1; o <= 2; o <<= 1) {
            sum0 += __shfl_xor_sync(0xffffffffu, sum0, o);
            sum1 += __shfl_xor_sync(0xffffffffu, sum1, o);
        }
        lrow[0] = lrow[0] * corr0 + sum0;
        lrow[1] = lrow[1] * corr1 + sum1;
        #pragma unroll
        for (int i = 0; i < 4; i++) {
            oacc[i][0] *= corr0; oacc[i][1] *= corr0;
            oacc[i][2] *= corr1; oacc[i][3] *= corr1;
        }
        // stage P (raw floats; truncated by mma)
        float* Pw = Ps + w * 16 * AP_STRIDE;
        #pragma unroll
        for (int nf = 0; nf < 8; nf++) {
            int col = nf * 8 + 2 * t;
            Pw[g * AP_STRIDE + col]           = s[nf][0];
            Pw[g * AP_STRIDE + col + 1]       = s[nf][1];
            Pw[(g + 8) * AP_STRIDE + col]     = s[nf][2];
            Pw[(g + 8) * AP_STRIDE + col + 1] = s[nf][3];
        }
        __syncwarp();
        const unsigned* Pu = (const unsigned*)Pw;
        // O += P V
        #pragma unroll
        for (int ks2 = 0; ks2 < 8; ks2++) {
            int kk = ks2 * 8;
            unsigned a0 = Pu[g * AP_STRIDE + kk + t];
            unsigned a1 = Pu[(g + 8) * AP_STRIDE + kk + t];
            unsigned a2 = Pu[g * AP_STRIDE + kk + t + 4];
            unsigned a3 = Pu[(g + 8) * AP_STRIDE + kk + t + 4];
            #pragma unroll
            for (int nf2 = 0; nf2 < 4; nf2++) {
                unsigned b0 = Vb[(kk + t)     * AV_STRIDE + nf2 * 8 + g];
                unsigned b1 = Vb[(kk + t + 4) * AV_STRIDE + nf2 * 8 + g];
                mma_tf32(oacc[nf2], a0, a1, a2, a3, b0, b1);
            }
        }
        __syncthreads();
    }
    float inv0 = 1.f / lrow[0], inv1 = 1.f / lrow[1];
    #pragma unroll
    for (int nf2 = 0; nf2 < 4; nf2++) {
        int feat = nf2 * 8 + 2 * t;
        if (r0g < Tt)
            *(float2*)(out + ((size_t)(b * Tt + r0g)) * 256 + h * 32 + feat) =
                make_float2(oacc[nf2][0] * inv0, oacc[nf2][1] * inv0);
        if (r1g < Tt)
            *(float2*)(out + ((size_t)(b * Tt + r1g)) * 256 + h * 32 + feat) =
                make_float2(oacc[nf2][2] * inv1, oacc[nf2][3] * inv1);
    }
}

__global__ void copy_kernel(float* __restrict__ out) {
    int i = blockIdx.x * 256 + threadIdx.x;
    if (i < Mrows * Dd) out[i] = g_x[i];
}

// ---------------------------------------------------------------------------
extern "C" void kernel_launch(void* const* d_in, const int* in_sizes, int n_in,
                              void* d_out, int out_size) {
    const float* nf       = (const float*)d_in[0];
    const int*   adj      = (const int*)  d_in[1];
    const float* dist     = (const float*)d_in[2];
    const float* eoh      = (const float*)d_in[3];
    const float* npw      = (const float*)d_in[4];
    const float* npb      = (const float*)d_in[5];
    const float* cls      = (const float*)d_in[6];
    const float* etw      = (const float*)d_in[7];
    const float* noedge   = (const float*)d_in[8];
    const float* degscale = (const float*)d_in[9];
    const float* gamma    = (const float*)d_in[10];
    const float* v2n      = (const float*)d_in[11];
    const float* n2v      = (const float*)d_in[12];
    const float* vself    = (const float*)d_in[13];
    const float* ln1g = (const float*)d_in[14]; const float* ln1b = (const float*)d_in[15];
    const float* qw   = (const float*)d_in[16]; const float* qb   = (const float*)d_in[17];
    const float* kw   = (const float*)d_in[18]; const float* kb   = (const float*)d_in[19];
    const float* vw   = (const float*)d_in[20]; const float* vb   = (const float*)d_in[21];
    const float* ow   = (const float*)d_in[22]; const float* ob   = (const float*)d_in[23];
    const float* ln2g = (const float*)d_in[24]; const float* ln2b = (const float*)d_in[25];
    const float* fc1w = (const float*)d_in[26]; const float* fc1b = (const float*)d_in[27];
    const float* fc2w = (const float*)d_in[28]; const float* fc2b = (const float*)d_in[29];

    float *p_x, *p_xn, *p_q, *p_k, *p_v, *p_att, *p_m1, *p_bias;
    cudaGetSymbolAddress((void**)&p_x,    g_x);
    cudaGetSymbolAddress((void**)&p_xn,   g_xn);
    cudaGetSymbolAddress((void**)&p_q,    g_q);
    cudaGetSymbolAddress((void**)&p_k,    g_k);
    cudaGetSymbolAddress((void**)&p_v,    g_v);
    cudaGetSymbolAddress((void**)&p_att,  g_att);
    cudaGetSymbolAddress((void**)&p_m1,   g_m1);
    cudaGetSymbolAddress((void**)&p_bias, g_bias);

    cudaFuncSetAttribute(gemm_qkv,    cudaFuncAttributeMaxDynamicSharedMemorySize, GEMM_SMEM);
    cudaFuncSetAttribute(gemm_one<1>, cudaFuncAttributeMaxDynamicSharedMemorySize, GEMM_SMEM);
    cudaFuncSetAttribute(gemm_one<2>, cudaFuncAttributeMaxDynamicSharedMemorySize, GEMM_SMEM);
    cudaFuncSetAttribute(attn_tc,     cudaFuncAttributeMaxDynamicSharedMemorySize, ATTN_SMEM);

    deg_kernel<<<(Bq * Nn) / 8, 256>>>(adj);
    degmax_kernel<<<Bq, 256>>>();
    bias_edge_kernel<<<dim3(Nn, Bq), 256>>>(adj, dist, eoh, etw, noedge, degscale, gamma);
    bias_fill_kernel<<<Bq, 256>>>(v2n, n2v, vself);

    proj_kernel<<<dim3(Tt, Bq), 256>>>(nf, npw, npb, cls);

    dim3 ggrid (2, (Mrows + 127) / 128);    // (2, 49)
    dim3 qgrid (6, (Mrows + 127) / 128);    // (6, 49)
    dim3 agrid (Bq * Hh, (Tt + 127) / 128); // (64, 7)
    for (int l = 0; l < Ll; l++) {
        size_t wo = (size_t)l * Dd * Dd;
        size_t bo = (size_t)l * Dd;
        ln_kernel<<<Mrows / 8, 256>>>(p_x, ln1g + bo, ln1b + bo, p_xn);
        gemm_qkv<<<qgrid, 256, GEMM_SMEM>>>(p_xn, qw + wo, qb + bo, p_q,
                                            kw + wo, kb + bo, p_k,
                                            vw + wo, vb + bo, p_v);
        attn_tc<<<agrid, 256, ATTN_SMEM>>>(p_q, p_k, p_v, p_bias, p_att);
        gemm_one<2><<<ggrid, 256, GEMM_SMEM>>>(p_att, ow + wo, ob + bo, p_x);
        ln_kernel<<<Mrows / 8, 256>>>(p_x, ln2g + bo, ln2b + bo, p_xn);
        gemm_one<1><<<ggrid, 256, GEMM_SMEM>>>(p_xn, fc1w + wo, fc1b + bo, p_m1);
        gemm_one<2><<<ggrid, 256, GEMM_SMEM>>>(p_m1, fc2w + wo, fc2b + bo, p_x);
    }
    copy_kernel<<<(Mrows * Dd + 255) / 256, 256>>>((float*)d_out);
}